// round 13
// baseline (speedup 1.0000x reference)
#include <cuda_runtime.h>
#include <cuda_fp16.h>
#include <cuda_bf16.h>

#define NN 100000
#define NE 3200000
#define ETOT (NE + NN)
#define PAD 128               // slots per dst bucket (max in-degree << 128)
#define FULL 0xffffffffu
#define LOG2E 1.44269504088896f
#define NEGBIG (-1e30f)
#define NBINS 130             // degree bins 0..129 (deg in [1,128])

// ---- scratch (sentinel row NN appended where needed) ----
__device__ __half2 g_hA[(NN + 1) * 16];   // feature buffer A (fp16 pairs)
__device__ __half2 g_hB[(NN + 1) * 16];   // feature buffer B
__device__ float   g_als[2 * (NN + 1)];   // per-head PLANAR src logits (log2e-scaled)
__device__ float   g_ald[NN * 2];         // per-node dst logits (interleaved, scaled)
__device__ int     g_cursor[NN];          // scatter cursors (post-scatter = degree)
__device__ int     g_esrc[NN * PAD];      // padded dst-bucket edge lists
__device__ int     g_bins[NBINS];         // degree histogram -> offsets
__device__ int     g_order[NN];           // nodes sorted by degree

__device__ __forceinline__ float ex2f(float x) {
    float r;
    asm("ex2.approx.f32 %0, %1;" : "=f"(r) : "f"(x));
    return r;
}

__device__ __forceinline__ __half2 shfl_xor_h2(__half2 v, int m) {
    unsigned u = *(unsigned*)&v;
    u = __shfl_xor_sync(FULL, u, m);
    return *(__half2*)&u;
}

// ===========================================================================
// CSR build + degree counting-sort
// ===========================================================================
__global__ void zero_kernel(int* __restrict__ cursor, int* __restrict__ bins) {
    int i = blockIdx.x * blockDim.x + threadIdx.x;
    if (i < NN) cursor[i] = 0;
    if (i < NBINS) bins[i] = 0;
}

__global__ void scatter_kernel(const int* __restrict__ ei, int* __restrict__ cursor,
                               int* __restrict__ esrc) {
    int e = blockIdx.x * blockDim.x + threadIdx.x;
    if (e >= ETOT) return;
    int src, dst;
    if (e < NE) { src = ei[e]; dst = ei[NE + e]; }
    else        { src = dst = e - NE; }
    int p = atomicAdd(&cursor[dst], 1);
    if (p < PAD) esrc[dst * PAD + p] = src;
}

__global__ void hist_kernel(const int* __restrict__ cursor, int* __restrict__ bins) {
    int i = blockIdx.x * blockDim.x + threadIdx.x;
    if (i >= NN) return;
    int deg = min(cursor[i], PAD);
    atomicAdd(&bins[deg], 1);
}

__global__ void scan_bins_kernel(int* __restrict__ bins) {
    __shared__ int sh[256];
    int t = threadIdx.x;
    int v = (t < NBINS) ? bins[t] : 0;
    sh[t] = v;
    __syncthreads();
#pragma unroll
    for (int o = 1; o < 256; o <<= 1) {
        int tmp = (t >= o) ? sh[t - o] : 0;
        __syncthreads();
        sh[t] += tmp;
        __syncthreads();
    }
    if (t < NBINS) bins[t] = sh[t] - v;     // exclusive offsets
}

__global__ void order_kernel(const int* __restrict__ cursor, int* __restrict__ bins,
                             int* __restrict__ order) {
    int i = blockIdx.x * blockDim.x + threadIdx.x;
    if (i >= NN) return;
    int deg = min(cursor[i], PAD);
    int pos = atomicAdd(&bins[deg], 1);
    order[pos] = i;
}

// ===========================================================================
// Layer-1 linear (runs after scatter): x[N,3] -> h fp16 + scaled logits.
// Also sentinel-fills bucket tails to a 16 multiple + sentinel rows.
// ===========================================================================
__global__ void lin1_kernel(const float* __restrict__ xin,
                            const float* __restrict__ W,
                            const float* __restrict__ aS,
                            const float* __restrict__ aD,
                            __half2* __restrict__ hout,
                            float* __restrict__ als, float* __restrict__ ald,
                            const int* __restrict__ cursor, int* __restrict__ esrc,
                            __half2* __restrict__ hother) {
    __shared__ float sW[3 * 32], sAS[32], sAD[32];
    for (int i = threadIdx.x; i < 3 * 32; i += blockDim.x) sW[i] = W[i];
    for (int i = threadIdx.x; i < 32; i += blockDim.x) {
        sAS[i] = aS[i] * LOG2E; sAD[i] = aD[i] * LOG2E;
    }
    __syncthreads();

    int n = blockIdx.x * blockDim.x + threadIdx.x;
    if (n >= NN) return;

    // sentinel bucket fill: pad to 16 multiple with node NN
    {
        int len = min(cursor[n], PAD);
        int len16 = (len + 15) & ~15;
        int* bucket = esrc + (size_t)n * PAD;
        for (int i = len; i < len16; i++) bucket[i] = NN;
    }
    if (n == 0) {
        als[NN] = NEGBIG; als[(NN + 1) + NN] = NEGBIG;
        const __half2 z = __floats2half2_rn(0.f, 0.f);
        for (int k = 0; k < 16; k++) { hout[(size_t)NN * 16 + k] = z; hother[(size_t)NN * 16 + k] = z; }
    }

    float x0 = xin[n * 3], x1 = xin[n * 3 + 1], x2 = xin[n * 3 + 2];
    float hreg[32];
#pragma unroll
    for (int o = 0; o < 32; o++)
        hreg[o] = fmaf(x0, sW[o], fmaf(x1, sW[32 + o], x2 * sW[64 + o]));

#pragma unroll
    for (int h = 0; h < 2; h++) {
        float s1 = 0.f, s2 = 0.f;
#pragma unroll
        for (int c = 0; c < 16; c++) {
            s1 = fmaf(hreg[h * 16 + c], sAS[h * 16 + c], s1);
            s2 = fmaf(hreg[h * 16 + c], sAD[h * 16 + c], s2);
        }
        als[h * (NN + 1) + n] = s1;     // planar per-head
        ald[n * 2 + h] = s2;
    }
#pragma unroll
    for (int k = 0; k < 16; k++)
        hout[(size_t)n * 16 + k] = __floats2half2_rn(hreg[2 * k], hreg[2 * k + 1]);
}

// ===========================================================================
// Hidden linear: h_in (fp16, 32 ch) -> COUT ch (fp16) + scaled logits
// ===========================================================================
template <int COUT, int H, int C>
__global__ void linH_kernel(const __half2* __restrict__ xin,
                            const float* __restrict__ W,
                            const float* __restrict__ aS,
                            const float* __restrict__ aD,
                            __half2* __restrict__ hout,
                            float* __restrict__ als, float* __restrict__ ald) {
    __shared__ float sW[32 * COUT], sAS[COUT], sAD[COUT];
    for (int i = threadIdx.x; i < 32 * COUT; i += blockDim.x) sW[i] = W[i];
    for (int i = threadIdx.x; i < COUT; i += blockDim.x) {
        sAS[i] = aS[i] * LOG2E; sAD[i] = aD[i] * LOG2E;
    }
    __syncthreads();

    int n = blockIdx.x * blockDim.x + threadIdx.x;
    if (n >= NN) return;
    if (n == 0) {
#pragma unroll
        for (int h = 0; h < H; h++) als[h * (NN + 1) + NN] = NEGBIG;
    }

    float xi[32];
#pragma unroll
    for (int k = 0; k < 16; k++) {
        float2 f = __half22float2(xin[(size_t)n * 16 + k]);
        xi[2 * k] = f.x; xi[2 * k + 1] = f.y;
    }
    float hreg[COUT];
#pragma unroll
    for (int o = 0; o < COUT; o++) {
        float a = 0.f;
#pragma unroll
        for (int c = 0; c < 32; c++) a = fmaf(xi[c], sW[c * COUT + o], a);
        hreg[o] = a;
    }
#pragma unroll
    for (int h = 0; h < H; h++) {
        float s1 = 0.f, s2 = 0.f;
#pragma unroll
        for (int c = 0; c < C; c++) {
            s1 = fmaf(hreg[h * C + c], sAS[h * C + c], s1);
            s2 = fmaf(hreg[h * C + c], sAD[h * C + c], s2);
        }
        als[h * (NN + 1) + n] = s1;     // planar per-head
        ald[n * H + h] = s2;
    }
#pragma unroll
    for (int k = 0; k < COUT / 2; k++)
        hout[(size_t)n * (COUT / 2) + k] = __floats2half2_rn(hreg[2 * k], hreg[2 * k + 1]);
}

// ===========================================================================
// Aggregation, 32 channels (H=2,C=16): one warp per dst node, nodes taken in
// degree-sorted order (warps in a CTA have near-equal trip counts). quad =
// lane&3 owns channels 8q..8q+7; eslot = lane>>2; 16 edges per iteration,
// single-stage software pipeline. Planar als (head = quad>>1) -> no SEL.
// fp16 HFMA2 accumulation; ssum fp32. Sentinel-padded (no predicates).
// ===========================================================================
__global__ void __launch_bounds__(128)
agg32h_kernel(const int* __restrict__ cnt,
              const int* __restrict__ order,
              const int* __restrict__ esrc,
              const float* __restrict__ als,
              const float2* __restrict__ ald,
              const uint4* __restrict__ hin4,
              const float* __restrict__ bias,
              uint4* __restrict__ hout4) {
    int widx = (blockIdx.x * blockDim.x + threadIdx.x) >> 5;
    int lane = threadIdx.x & 31;
    if (widx >= NN) return;
    int w = order[widx];
    int quad  = lane & 3;
    int eslot = lane >> 2;
    int head  = quad >> 1;
    const float* alsP = als + head * (NN + 1);
    int len16 = (min(cnt[w], PAD) + 15) & ~15;
    const int* bucket = esrc + (size_t)w * PAD + eslot;
    float2 adv2 = ald[w];
    float adv = head ? adv2.y : adv2.x;
    __half2 haccA[4], haccB[4];
    const __half2 hz = __floats2half2_rn(0.f, 0.f);
#pragma unroll
    for (int k = 0; k < 4; k++) { haccA[k] = hz; haccB[k] = hz; }
    float ssum = 0.f;

    // prologue: load iteration 0 (always valid: len16 >= 16 via self-loop)
    int sA = bucket[0];
    int sB = bucket[8];
    float aA = alsP[sA];
    float aB = alsP[sB];
    uint4 fA = hin4[(size_t)sA * 4 + quad];
    uint4 fB = hin4[(size_t)sB * 4 + quad];

    for (int base = 16; base < len16; base += 16) {
        // ---- prefetch next iteration ----
        int nsA = bucket[base];
        int nsB = bucket[base + 8];
        float naA = alsP[nsA];
        float naB = alsP[nsB];
        uint4 nfA = hin4[(size_t)nsA * 4 + quad];
        uint4 nfB = hin4[(size_t)nsB * 4 + quad];

        // ---- compute current ----
        float lA = aA + adv;
        float exA = ex2f(fmaxf(lA, 0.2f * lA));
        float lB = aB + adv;
        float exB = ex2f(fmaxf(lB, 0.2f * lB));
        ssum += exA + exB;
        __half2 eA = __float2half2_rn(exA);
        __half2 eB = __float2half2_rn(exB);
        const __half2* pA = (const __half2*)&fA;
        const __half2* pB = (const __half2*)&fB;
#pragma unroll
        for (int k = 0; k < 4; k++) {
            haccA[k] = __hfma2(eA, pA[k], haccA[k]);
            haccB[k] = __hfma2(eB, pB[k], haccB[k]);
        }
        // ---- rotate ----
        aA = naA; aB = naB; fA = nfA; fB = nfB;
    }
    // epilogue: compute last staged iteration
    {
        float lA = aA + adv;
        float exA = ex2f(fmaxf(lA, 0.2f * lA));
        float lB = aB + adv;
        float exB = ex2f(fmaxf(lB, 0.2f * lB));
        ssum += exA + exB;
        __half2 eA = __float2half2_rn(exA);
        __half2 eB = __float2half2_rn(exB);
        const __half2* pA = (const __half2*)&fA;
        const __half2* pB = (const __half2*)&fB;
#pragma unroll
        for (int k = 0; k < 4; k++) {
            haccA[k] = __hfma2(eA, pA[k], haccA[k]);
            haccB[k] = __hfma2(eB, pB[k], haccB[k]);
        }
    }

    __half2 hacc[4];
#pragma unroll
    for (int k = 0; k < 4; k++) hacc[k] = __hadd2(haccA[k], haccB[k]);

    // reduce over the 8 edge slots (xor lane bits 2,3,4)
    ssum += __shfl_xor_sync(FULL, ssum, 4);
    ssum += __shfl_xor_sync(FULL, ssum, 8);
    ssum += __shfl_xor_sync(FULL, ssum, 16);
#pragma unroll
    for (int k = 0; k < 4; k++) {
        hacc[k] = __hadd2(hacc[k], shfl_xor_h2(hacc[k], 4));
        hacc[k] = __hadd2(hacc[k], shfl_xor_h2(hacc[k], 8));
        hacc[k] = __hadd2(hacc[k], shfl_xor_h2(hacc[k], 16));
    }
    if (eslot == 0) {
        float inv = 1.f / (ssum + 1e-16f);
        float2 f0 = __half22float2(hacc[0]);
        float2 f1 = __half22float2(hacc[1]);
        float2 f2 = __half22float2(hacc[2]);
        float2 f3 = __half22float2(hacc[3]);
        const float4* b4 = (const float4*)bias;
        float4 bA = b4[quad * 2], bB = b4[quad * 2 + 1];
        float v0 = f0.x * inv + bA.x; v0 = v0 > 0.f ? v0 : (__expf(v0) - 1.f);
        float v1 = f0.y * inv + bA.y; v1 = v1 > 0.f ? v1 : (__expf(v1) - 1.f);
        float v2 = f1.x * inv + bA.z; v2 = v2 > 0.f ? v2 : (__expf(v2) - 1.f);
        float v3 = f1.y * inv + bA.w; v3 = v3 > 0.f ? v3 : (__expf(v3) - 1.f);
        float v4 = f2.x * inv + bB.x; v4 = v4 > 0.f ? v4 : (__expf(v4) - 1.f);
        float v5 = f2.y * inv + bB.y; v5 = v5 > 0.f ? v5 : (__expf(v5) - 1.f);
        float v6 = f3.x * inv + bB.z; v6 = v6 > 0.f ? v6 : (__expf(v6) - 1.f);
        float v7 = f3.y * inv + bB.w; v7 = v7 > 0.f ? v7 : (__expf(v7) - 1.f);
        uint4 o;
        __half2 h0 = __floats2half2_rn(v0, v1);
        __half2 h1 = __floats2half2_rn(v2, v3);
        __half2 h2 = __floats2half2_rn(v4, v5);
        __half2 h3 = __floats2half2_rn(v6, v7);
        o.x = *(const unsigned*)&h0; o.y = *(const unsigned*)&h1;
        o.z = *(const unsigned*)&h2; o.w = *(const unsigned*)&h3;
        hout4[(size_t)w * 4 + quad] = o;
    }
}

// ===========================================================================
// Final layer: H=1 C=8. 2 lanes per edge (pairi = lane&1), eslot = lane>>1,
// 16 edges per round, degree-sorted order, single-stage pipeline,
// fp16 HFMA2 accumulation. Fused elu + @Wo + bo.
// ===========================================================================
__global__ void __launch_bounds__(128)
agg_final_kernel(const int* __restrict__ cnt,
                 const int* __restrict__ order,
                 const int* __restrict__ esrc,
                 const float* __restrict__ als,
                 const float* __restrict__ ald,
                 const uint2* __restrict__ hin2,
                 const float* __restrict__ bias,
                 const float* __restrict__ Wo,
                 const float* __restrict__ bo,
                 float* __restrict__ out) {
    int widx = (blockIdx.x * blockDim.x + threadIdx.x) >> 5;
    int lane = threadIdx.x & 31;
    if (widx >= NN) return;
    int w = order[widx];
    int pairi = lane & 1;
    int eslot = lane >> 1;
    int len16 = (min(cnt[w], PAD) + 15) & ~15;
    const int* bucket = esrc + (size_t)w * PAD + eslot;
    float ad = ald[w];
    __half2 hacc[2];
    hacc[0] = __floats2half2_rn(0.f, 0.f);
    hacc[1] = hacc[0];
    float ssum = 0.f;

    // prologue
    int srcv = bucket[0];
    float av = als[srcv];
    uint2 f = hin2[(size_t)srcv * 2 + pairi];

    for (int base = 16; base < len16; base += 16) {
        int nsrc = bucket[base];
        float nav = als[nsrc];
        uint2 nf = hin2[(size_t)nsrc * 2 + pairi];

        float l = av + ad;
        float ex = ex2f(fmaxf(l, 0.2f * l));
        ssum += ex;
        __half2 e2 = __float2half2_rn(ex);
        const __half2* p = (const __half2*)&f;
        hacc[0] = __hfma2(e2, p[0], hacc[0]);
        hacc[1] = __hfma2(e2, p[1], hacc[1]);

        av = nav; f = nf;
    }
    {
        float l = av + ad;
        float ex = ex2f(fmaxf(l, 0.2f * l));
        ssum += ex;
        __half2 e2 = __float2half2_rn(ex);
        const __half2* p = (const __half2*)&f;
        hacc[0] = __hfma2(e2, p[0], hacc[0]);
        hacc[1] = __hfma2(e2, p[1], hacc[1]);
    }

    // reduce over 16 eslots (xor lane bits 1..4)
    ssum += __shfl_xor_sync(FULL, ssum, 2);
    ssum += __shfl_xor_sync(FULL, ssum, 4);
    ssum += __shfl_xor_sync(FULL, ssum, 8);
    ssum += __shfl_xor_sync(FULL, ssum, 16);
#pragma unroll
    for (int k = 0; k < 2; k++) {
        hacc[k] = __hadd2(hacc[k], shfl_xor_h2(hacc[k], 2));
        hacc[k] = __hadd2(hacc[k], shfl_xor_h2(hacc[k], 4));
        hacc[k] = __hadd2(hacc[k], shfl_xor_h2(hacc[k], 8));
        hacc[k] = __hadd2(hacc[k], shfl_xor_h2(hacc[k], 16));
    }
    if (eslot == 0) {
        float inv = 1.f / (ssum + 1e-16f);
        float2 f0 = __half22float2(hacc[0]);
        float2 f1 = __half22float2(hacc[1]);
        float a[4] = {f0.x, f0.y, f1.x, f1.y};
        float o = 0.f;
#pragma unroll
        for (int k = 0; k < 4; k++) {
            int ch = pairi * 4 + k;
            float v = a[k] * inv + bias[ch];
            v = v > 0.f ? v : (__expf(v) - 1.f);
            o = fmaf(v, Wo[ch], o);
        }
        o += __shfl_xor_sync(FULL, o, 1);
        if (pairi == 0) out[w] = o + bo[0];
    }
}

// ===========================================================================
extern "C" void kernel_launch(void* const* d_in, const int* in_sizes, int n_in,
                              void* d_out, int out_size) {
    const float* x   = (const float*)d_in[0];
    const int*   ei  = (const int*)d_in[1];
    const float* W1  = (const float*)d_in[2];
    const float* as1 = (const float*)d_in[3];
    const float* ad1 = (const float*)d_in[4];
    const float* b1  = (const float*)d_in[5];
    const float* W2  = (const float*)d_in[6];
    const float* as2 = (const float*)d_in[7];
    const float* ad2 = (const float*)d_in[8];
    const float* b2  = (const float*)d_in[9];
    const float* W3  = (const float*)d_in[10];
    const float* as3 = (const float*)d_in[11];
    const float* ad3 = (const float*)d_in[12];
    const float* b3  = (const float*)d_in[13];
    const float* Wo  = (const float*)d_in[14];
    const float* bo  = (const float*)d_in[15];
    float* out = (float*)d_out;

    __half2 *hA, *hB;
    float *als, *ald;
    int *cursor, *esrc, *bins, *order;
    cudaGetSymbolAddress((void**)&hA, g_hA);
    cudaGetSymbolAddress((void**)&hB, g_hB);
    cudaGetSymbolAddress((void**)&als, g_als);
    cudaGetSymbolAddress((void**)&ald, g_ald);
    cudaGetSymbolAddress((void**)&cursor, g_cursor);
    cudaGetSymbolAddress((void**)&esrc, g_esrc);
    cudaGetSymbolAddress((void**)&bins, g_bins);
    cudaGetSymbolAddress((void**)&order, g_order);

    const int NB = 256;
    const int gN = (NN + NB - 1) / NB;
    const int gE = (ETOT + NB - 1) / NB;
    const int NBW = 128;
    const int gW = (NN * 32 + NBW - 1) / NBW;   // one warp per node

    // ---- padded-bucket CSR build + degree counting-sort ----
    zero_kernel<<<gN, NB>>>(cursor, bins);
    scatter_kernel<<<gE, NB>>>(ei, cursor, esrc);
    hist_kernel<<<gN, NB>>>(cursor, bins);
    scan_bins_kernel<<<1, 256>>>(bins);
    order_kernel<<<gN, NB>>>(cursor, bins, order);

    // ---- Layer 1 (also sentinel-pads buckets) ----
    lin1_kernel<<<gN, NB>>>(x, W1, as1, ad1, hA, als, ald, cursor, esrc, hB);
    agg32h_kernel<<<gW, NBW>>>(cursor, order, esrc, als, (const float2*)ald,
                               (const uint4*)hA, b1, (uint4*)hB);

    // ---- Layer 2 ----
    linH_kernel<32, 2, 16><<<gN, NB>>>(hB, W2, as2, ad2, hA, als, ald);
    agg32h_kernel<<<gW, NBW>>>(cursor, order, esrc, als, (const float2*)ald,
                               (const uint4*)hA, b2, (uint4*)hB);

    // ---- Layer 3 + output projection ----
    linH_kernel<8, 1, 8><<<gN, NB>>>(hB, W3, as3, ad3, hA, als, ald);
    agg_final_kernel<<<gW, NBW>>>(cursor, order, esrc, als, ald,
                                  (const uint2*)hA, b3, Wo, bo, out);
}

// round 14
// speedup vs baseline: 1.2428x; 1.2428x over previous
#include <cuda_runtime.h>
#include <cuda_fp16.h>
#include <cuda_bf16.h>

#define NN 100000
#define NE 3200000
#define ETOT (NE + NN)
#define PAD 128               // slots per dst bucket (max in-degree << 128)
#define FULL 0xffffffffu
#define LOG2E 1.44269504088896f
#define NEGBIG (-1e30f)

// ---- scratch (sentinel row NN appended where needed) ----
__device__ __half2 g_hA[(NN + 1) * 16];   // feature buffer A (fp16 pairs)
__device__ __half2 g_hB[(NN + 1) * 16];   // feature buffer B
__device__ float   g_als[2 * (NN + 1)];   // per-head PLANAR src logits (log2e-scaled)
__device__ float   g_ald[NN * 2];         // per-node dst logits (interleaved, scaled)
__device__ int     g_cursor[NN];          // scatter cursors (post-scatter = degree)
__device__ int     g_esrc[NN * PAD];      // padded dst-bucket edge lists

__device__ __forceinline__ float ex2f(float x) {
    float r;
    asm("ex2.approx.f32 %0, %1;" : "=f"(r) : "f"(x));
    return r;
}

__device__ __forceinline__ __half2 shfl_xor_h2(__half2 v, int m) {
    unsigned u = *(unsigned*)&v;
    u = __shfl_xor_sync(FULL, u, m);
    return *(__half2*)&u;
}

// ===========================================================================
// CSR build: zero cursors, then scatter into padded buckets
// ===========================================================================
__global__ void zero_cursor_kernel(int* __restrict__ cursor) {
    int i = blockIdx.x * blockDim.x + threadIdx.x;
    if (i < NN) cursor[i] = 0;
}

__global__ void scatter_kernel(const int* __restrict__ ei, int* __restrict__ cursor,
                               int* __restrict__ esrc) {
    int e = blockIdx.x * blockDim.x + threadIdx.x;
    if (e >= ETOT) return;
    int src, dst;
    if (e < NE) { src = ei[e]; dst = ei[NE + e]; }
    else        { src = dst = e - NE; }
    int p = atomicAdd(&cursor[dst], 1);
    if (p < PAD) esrc[dst * PAD + p] = src;
}

// ===========================================================================
// Layer-1 linear (runs after scatter): x[N,3] -> h fp16 + scaled logits.
// Also sentinel-fills bucket tails to a 16 multiple + sentinel rows.
// ===========================================================================
__global__ void lin1_kernel(const float* __restrict__ xin,
                            const float* __restrict__ W,
                            const float* __restrict__ aS,
                            const float* __restrict__ aD,
                            __half2* __restrict__ hout,
                            float* __restrict__ als, float* __restrict__ ald,
                            const int* __restrict__ cursor, int* __restrict__ esrc,
                            __half2* __restrict__ hother) {
    __shared__ float sW[3 * 32], sAS[32], sAD[32];
    for (int i = threadIdx.x; i < 3 * 32; i += blockDim.x) sW[i] = W[i];
    for (int i = threadIdx.x; i < 32; i += blockDim.x) {
        sAS[i] = aS[i] * LOG2E; sAD[i] = aD[i] * LOG2E;
    }
    __syncthreads();

    int n = blockIdx.x * blockDim.x + threadIdx.x;
    if (n >= NN) return;

    // sentinel bucket fill: pad to 16 multiple with node NN
    {
        int len = min(cursor[n], PAD);
        int len16 = (len + 15) & ~15;
        int* bucket = esrc + (size_t)n * PAD;
        for (int i = len; i < len16; i++) bucket[i] = NN;
    }
    if (n == 0) {
        als[NN] = NEGBIG; als[(NN + 1) + NN] = NEGBIG;
        const __half2 z = __floats2half2_rn(0.f, 0.f);
        for (int k = 0; k < 16; k++) { hout[(size_t)NN * 16 + k] = z; hother[(size_t)NN * 16 + k] = z; }
    }

    float x0 = xin[n * 3], x1 = xin[n * 3 + 1], x2 = xin[n * 3 + 2];
    float hreg[32];
#pragma unroll
    for (int o = 0; o < 32; o++)
        hreg[o] = fmaf(x0, sW[o], fmaf(x1, sW[32 + o], x2 * sW[64 + o]));

#pragma unroll
    for (int h = 0; h < 2; h++) {
        float s1 = 0.f, s2 = 0.f;
#pragma unroll
        for (int c = 0; c < 16; c++) {
            s1 = fmaf(hreg[h * 16 + c], sAS[h * 16 + c], s1);
            s2 = fmaf(hreg[h * 16 + c], sAD[h * 16 + c], s2);
        }
        als[h * (NN + 1) + n] = s1;     // planar per-head
        ald[n * 2 + h] = s2;
    }
#pragma unroll
    for (int k = 0; k < 16; k++)
        hout[(size_t)n * 16 + k] = __floats2half2_rn(hreg[2 * k], hreg[2 * k + 1]);
}

// ===========================================================================
// Hidden linear: h_in (fp16, 32 ch) -> COUT ch (fp16) + scaled logits
// ===========================================================================
template <int COUT, int H, int C>
__global__ void linH_kernel(const __half2* __restrict__ xin,
                            const float* __restrict__ W,
                            const float* __restrict__ aS,
                            const float* __restrict__ aD,
                            __half2* __restrict__ hout,
                            float* __restrict__ als, float* __restrict__ ald) {
    __shared__ float sW[32 * COUT], sAS[COUT], sAD[COUT];
    for (int i = threadIdx.x; i < 32 * COUT; i += blockDim.x) sW[i] = W[i];
    for (int i = threadIdx.x; i < COUT; i += blockDim.x) {
        sAS[i] = aS[i] * LOG2E; sAD[i] = aD[i] * LOG2E;
    }
    __syncthreads();

    int n = blockIdx.x * blockDim.x + threadIdx.x;
    if (n >= NN) return;
    if (n == 0) {
#pragma unroll
        for (int h = 0; h < H; h++) als[h * (NN + 1) + NN] = NEGBIG;
    }

    float xi[32];
#pragma unroll
    for (int k = 0; k < 16; k++) {
        float2 f = __half22float2(xin[(size_t)n * 16 + k]);
        xi[2 * k] = f.x; xi[2 * k + 1] = f.y;
    }
    float hreg[COUT];
#pragma unroll
    for (int o = 0; o < COUT; o++) {
        float a = 0.f;
#pragma unroll
        for (int c = 0; c < 32; c++) a = fmaf(xi[c], sW[c * COUT + o], a);
        hreg[o] = a;
    }
#pragma unroll
    for (int h = 0; h < H; h++) {
        float s1 = 0.f, s2 = 0.f;
#pragma unroll
        for (int c = 0; c < C; c++) {
            s1 = fmaf(hreg[h * C + c], sAS[h * C + c], s1);
            s2 = fmaf(hreg[h * C + c], sAD[h * C + c], s2);
        }
        als[h * (NN + 1) + n] = s1;     // planar per-head
        ald[n * H + h] = s2;
    }
#pragma unroll
    for (int k = 0; k < COUT / 2; k++)
        hout[(size_t)n * (COUT / 2) + k] = __floats2half2_rn(hreg[2 * k], hreg[2 * k + 1]);
}

// ===========================================================================
// Aggregation, 32 channels (H=2,C=16): one warp per dst node (natural node
// order -> locality). quad = lane&3 owns channels 8q..8q+7; eslot = lane>>2;
// 16 edges per iteration, single-stage software pipeline. Planar als keyed by
// head = quad>>1 (no SELs). fp16 HFMA2 accumulation; ssum fp32.
// Sentinel-padded buckets (no predicates in the loop). 128-thread blocks.
// ===========================================================================
__global__ void __launch_bounds__(128)
agg32h_kernel(const int* __restrict__ cnt,
              const int* __restrict__ esrc,
              const float* __restrict__ als,
              const float2* __restrict__ ald,
              const uint4* __restrict__ hin4,
              const float* __restrict__ bias,
              uint4* __restrict__ hout4) {
    int w = (blockIdx.x * blockDim.x + threadIdx.x) >> 5;
    int lane = threadIdx.x & 31;
    if (w >= NN) return;
    int quad  = lane & 3;
    int eslot = lane >> 2;
    int head  = quad >> 1;
    const float* alsP = als + head * (NN + 1);
    int len16 = (min(cnt[w], PAD) + 15) & ~15;
    const int* bucket = esrc + (size_t)w * PAD + eslot;
    float2 adv2 = ald[w];
    float adv = head ? adv2.y : adv2.x;
    __half2 haccA[4], haccB[4];
    const __half2 hz = __floats2half2_rn(0.f, 0.f);
#pragma unroll
    for (int k = 0; k < 4; k++) { haccA[k] = hz; haccB[k] = hz; }
    float ssum = 0.f;

    // prologue: load iteration 0 (always valid: len16 >= 16 via self-loop)
    int sA = bucket[0];
    int sB = bucket[8];
    float aA = alsP[sA];
    float aB = alsP[sB];
    uint4 fA = hin4[(size_t)sA * 4 + quad];
    uint4 fB = hin4[(size_t)sB * 4 + quad];

    for (int base = 16; base < len16; base += 16) {
        // ---- prefetch next iteration ----
        int nsA = bucket[base];
        int nsB = bucket[base + 8];
        float naA = alsP[nsA];
        float naB = alsP[nsB];
        uint4 nfA = hin4[(size_t)nsA * 4 + quad];
        uint4 nfB = hin4[(size_t)nsB * 4 + quad];

        // ---- compute current ----
        float lA = aA + adv;
        float exA = ex2f(fmaxf(lA, 0.2f * lA));
        float lB = aB + adv;
        float exB = ex2f(fmaxf(lB, 0.2f * lB));
        ssum += exA + exB;
        __half2 eA = __float2half2_rn(exA);
        __half2 eB = __float2half2_rn(exB);
        const __half2* pA = (const __half2*)&fA;
        const __half2* pB = (const __half2*)&fB;
#pragma unroll
        for (int k = 0; k < 4; k++) {
            haccA[k] = __hfma2(eA, pA[k], haccA[k]);
            haccB[k] = __hfma2(eB, pB[k], haccB[k]);
        }
        // ---- rotate ----
        aA = naA; aB = naB; fA = nfA; fB = nfB;
    }
    // epilogue: compute last staged iteration
    {
        float lA = aA + adv;
        float exA = ex2f(fmaxf(lA, 0.2f * lA));
        float lB = aB + adv;
        float exB = ex2f(fmaxf(lB, 0.2f * lB));
        ssum += exA + exB;
        __half2 eA = __float2half2_rn(exA);
        __half2 eB = __float2half2_rn(exB);
        const __half2* pA = (const __half2*)&fA;
        const __half2* pB = (const __half2*)&fB;
#pragma unroll
        for (int k = 0; k < 4; k++) {
            haccA[k] = __hfma2(eA, pA[k], haccA[k]);
            haccB[k] = __hfma2(eB, pB[k], haccB[k]);
        }
    }

    __half2 hacc[4];
#pragma unroll
    for (int k = 0; k < 4; k++) hacc[k] = __hadd2(haccA[k], haccB[k]);

    // reduce over the 8 edge slots (xor lane bits 2,3,4)
    ssum += __shfl_xor_sync(FULL, ssum, 4);
    ssum += __shfl_xor_sync(FULL, ssum, 8);
    ssum += __shfl_xor_sync(FULL, ssum, 16);
#pragma unroll
    for (int k = 0; k < 4; k++) {
        hacc[k] = __hadd2(hacc[k], shfl_xor_h2(hacc[k], 4));
        hacc[k] = __hadd2(hacc[k], shfl_xor_h2(hacc[k], 8));
        hacc[k] = __hadd2(hacc[k], shfl_xor_h2(hacc[k], 16));
    }
    if (eslot == 0) {
        float inv = 1.f / (ssum + 1e-16f);
        float2 f0 = __half22float2(hacc[0]);
        float2 f1 = __half22float2(hacc[1]);
        float2 f2 = __half22float2(hacc[2]);
        float2 f3 = __half22float2(hacc[3]);
        const float4* b4 = (const float4*)bias;
        float4 bA = b4[quad * 2], bB = b4[quad * 2 + 1];
        float v0 = f0.x * inv + bA.x; v0 = v0 > 0.f ? v0 : (__expf(v0) - 1.f);
        float v1 = f0.y * inv + bA.y; v1 = v1 > 0.f ? v1 : (__expf(v1) - 1.f);
        float v2 = f1.x * inv + bA.z; v2 = v2 > 0.f ? v2 : (__expf(v2) - 1.f);
        float v3 = f1.y * inv + bA.w; v3 = v3 > 0.f ? v3 : (__expf(v3) - 1.f);
        float v4 = f2.x * inv + bB.x; v4 = v4 > 0.f ? v4 : (__expf(v4) - 1.f);
        float v5 = f2.y * inv + bB.y; v5 = v5 > 0.f ? v5 : (__expf(v5) - 1.f);
        float v6 = f3.x * inv + bB.z; v6 = v6 > 0.f ? v6 : (__expf(v6) - 1.f);
        float v7 = f3.y * inv + bB.w; v7 = v7 > 0.f ? v7 : (__expf(v7) - 1.f);
        uint4 o;
        __half2 h0 = __floats2half2_rn(v0, v1);
        __half2 h1 = __floats2half2_rn(v2, v3);
        __half2 h2 = __floats2half2_rn(v4, v5);
        __half2 h3 = __floats2half2_rn(v6, v7);
        o.x = *(const unsigned*)&h0; o.y = *(const unsigned*)&h1;
        o.z = *(const unsigned*)&h2; o.w = *(const unsigned*)&h3;
        hout4[(size_t)w * 4 + quad] = o;
    }
}

// ===========================================================================
// Final layer: H=1 C=8. 2 lanes per edge (pairi = lane&1 owns 4 channels via
// one uint2), eslot = lane>>1 -> 16 edges per round. Single-stage pipeline,
// fp16 HFMA2 accumulation. Fused elu + @Wo + bo. 128-thread blocks.
// ===========================================================================
__global__ void __launch_bounds__(128)
agg_final_kernel(const int* __restrict__ cnt,
                 const int* __restrict__ esrc,
                 const float* __restrict__ als,
                 const float* __restrict__ ald,
                 const uint2* __restrict__ hin2,
                 const float* __restrict__ bias,
                 const float* __restrict__ Wo,
                 const float* __restrict__ bo,
                 float* __restrict__ out) {
    int w = (blockIdx.x * blockDim.x + threadIdx.x) >> 5;
    int lane = threadIdx.x & 31;
    if (w >= NN) return;
    int pairi = lane & 1;
    int eslot = lane >> 1;
    int len16 = (min(cnt[w], PAD) + 15) & ~15;
    const int* bucket = esrc + (size_t)w * PAD + eslot;
    float ad = ald[w];
    __half2 hacc[2];
    hacc[0] = __floats2half2_rn(0.f, 0.f);
    hacc[1] = hacc[0];
    float ssum = 0.f;

    // prologue
    int srcv = bucket[0];
    float av = als[srcv];
    uint2 f = hin2[(size_t)srcv * 2 + pairi];

    for (int base = 16; base < len16; base += 16) {
        int nsrc = bucket[base];
        float nav = als[nsrc];
        uint2 nf = hin2[(size_t)nsrc * 2 + pairi];

        float l = av + ad;
        float ex = ex2f(fmaxf(l, 0.2f * l));
        ssum += ex;
        __half2 e2 = __float2half2_rn(ex);
        const __half2* p = (const __half2*)&f;
        hacc[0] = __hfma2(e2, p[0], hacc[0]);
        hacc[1] = __hfma2(e2, p[1], hacc[1]);

        av = nav; f = nf;
    }
    {
        float l = av + ad;
        float ex = ex2f(fmaxf(l, 0.2f * l));
        ssum += ex;
        __half2 e2 = __float2half2_rn(ex);
        const __half2* p = (const __half2*)&f;
        hacc[0] = __hfma2(e2, p[0], hacc[0]);
        hacc[1] = __hfma2(e2, p[1], hacc[1]);
    }

    // reduce over 16 eslots (xor lane bits 1..4)
    ssum += __shfl_xor_sync(FULL, ssum, 2);
    ssum += __shfl_xor_sync(FULL, ssum, 4);
    ssum += __shfl_xor_sync(FULL, ssum, 8);
    ssum += __shfl_xor_sync(FULL, ssum, 16);
#pragma unroll
    for (int k = 0; k < 2; k++) {
        hacc[k] = __hadd2(hacc[k], shfl_xor_h2(hacc[k], 2));
        hacc[k] = __hadd2(hacc[k], shfl_xor_h2(hacc[k], 4));
        hacc[k] = __hadd2(hacc[k], shfl_xor_h2(hacc[k], 8));
        hacc[k] = __hadd2(hacc[k], shfl_xor_h2(hacc[k], 16));
    }
    if (eslot == 0) {
        float inv = 1.f / (ssum + 1e-16f);
        float2 f0 = __half22float2(hacc[0]);
        float2 f1 = __half22float2(hacc[1]);
        float a[4] = {f0.x, f0.y, f1.x, f1.y};
        float o = 0.f;
#pragma unroll
        for (int k = 0; k < 4; k++) {
            int ch = pairi * 4 + k;
            float v = a[k] * inv + bias[ch];
            v = v > 0.f ? v : (__expf(v) - 1.f);
            o = fmaf(v, Wo[ch], o);
        }
        o += __shfl_xor_sync(FULL, o, 1);
        if (pairi == 0) out[w] = o + bo[0];
    }
}

// ===========================================================================
extern "C" void kernel_launch(void* const* d_in, const int* in_sizes, int n_in,
                              void* d_out, int out_size) {
    const float* x   = (const float*)d_in[0];
    const int*   ei  = (const int*)d_in[1];
    const float* W1  = (const float*)d_in[2];
    const float* as1 = (const float*)d_in[3];
    const float* ad1 = (const float*)d_in[4];
    const float* b1  = (const float*)d_in[5];
    const float* W2  = (const float*)d_in[6];
    const float* as2 = (const float*)d_in[7];
    const float* ad2 = (const float*)d_in[8];
    const float* b2  = (const float*)d_in[9];
    const float* W3  = (const float*)d_in[10];
    const float* as3 = (const float*)d_in[11];
    const float* ad3 = (const float*)d_in[12];
    const float* b3  = (const float*)d_in[13];
    const float* Wo  = (const float*)d_in[14];
    const float* bo  = (const float*)d_in[15];
    float* out = (float*)d_out;

    __half2 *hA, *hB;
    float *als, *ald;
    int *cursor, *esrc;
    cudaGetSymbolAddress((void**)&hA, g_hA);
    cudaGetSymbolAddress((void**)&hB, g_hB);
    cudaGetSymbolAddress((void**)&als, g_als);
    cudaGetSymbolAddress((void**)&ald, g_ald);
    cudaGetSymbolAddress((void**)&cursor, g_cursor);
    cudaGetSymbolAddress((void**)&esrc, g_esrc);

    const int NB = 256;
    const int gN = (NN + NB - 1) / NB;
    const int gE = (ETOT + NB - 1) / NB;
    const int NBW = 128;
    const int gW = (NN * 32 + NBW - 1) / NBW;   // one warp per node

    // ---- padded-bucket CSR build ----
    zero_cursor_kernel<<<gN, NB>>>(cursor);
    scatter_kernel<<<gE, NB>>>(ei, cursor, esrc);

    // ---- Layer 1 (also sentinel-pads buckets) ----
    lin1_kernel<<<gN, NB>>>(x, W1, as1, ad1, hA, als, ald, cursor, esrc, hB);
    agg32h_kernel<<<gW, NBW>>>(cursor, esrc, als, (const float2*)ald,
                               (const uint4*)hA, b1, (uint4*)hB);

    // ---- Layer 2 ----
    linH_kernel<32, 2, 16><<<gN, NB>>>(hB, W2, as2, ad2, hA, als, ald);
    agg32h_kernel<<<gW, NBW>>>(cursor, esrc, als, (const float2*)ald,
                               (const uint4*)hA, b2, (uint4*)hB);

    // ---- Layer 3 + output projection ----
    linH_kernel<8, 1, 8><<<gN, NB>>>(hB, W3, as3, ad3, hA, als, ald);
    agg_final_kernel<<<gW, NBW>>>(cursor, esrc, als, ald,
                                  (const uint2*)hA, b3, Wo, bo, out);
}